// round 1
// baseline (speedup 1.0000x reference)
#include <cuda_runtime.h>
#include <cstdint>

#define D 64
#define MAXN 100000
#define MAXE 1600000
#define EPB 128   // edges per block

// Scratch (static device globals; no runtime allocation allowed)
__device__ float g_h[(size_t)MAXN * D];    // h = node_h @ W_fc^T
__device__ float g_num[(size_t)MAXN * D];  // sum ex*(h[src]+eh) per (dst, ch)
__device__ float g_den[(size_t)MAXN * D];  // sum ex per (dst, ch)

typedef unsigned long long ull;

__device__ __forceinline__ ull fma2(ull a, ull b, ull c) {
    ull d;
    asm("fma.rn.f32x2 %0, %1, %2, %3;" : "=l"(d) : "l"(a), "l"(b), "l"(c));
    return d;
}
__device__ __forceinline__ float2 unpack2(ull v) {
    float2 r;
    asm("mov.b64 {%0, %1}, %2;" : "=f"(r.x), "=f"(r.y) : "l"(v));
    return r;
}

// ---------------------------------------------------------------------------
// Zero the accumulators (num/den), float4-vectorized.
__global__ void k_zero(int n4) {  // n4 = N*D/4
    int i = blockIdx.x * blockDim.x + threadIdx.x;
    int stride = gridDim.x * blockDim.x;
    float4 z = make_float4(0.f, 0.f, 0.f, 0.f);
    float4* a = (float4*)g_num;
    float4* b = (float4*)g_den;
    for (; i < n4; i += stride) { a[i] = z; b[i] = z; }
}

// ---------------------------------------------------------------------------
// g_h[n, j] = sum_k node_h[n, k] * W_fc[j, k]
__global__ __launch_bounds__(128) void k_node_gemm(
    const float* __restrict__ X, const float* __restrict__ W, int n) {
    __shared__ float sW[D * D];
    for (int i = threadIdx.x; i < D * D; i += blockDim.x) sW[i] = W[i];
    __syncthreads();
    int r = blockIdx.x * blockDim.x + threadIdx.x;
    if (r >= n) return;

    ull xp[D / 2];
    const ulonglong2* xr = (const ulonglong2*)(X + (size_t)r * D);
#pragma unroll
    for (int i = 0; i < D / 4; i++) { ulonglong2 v = xr[i]; xp[2 * i] = v.x; xp[2 * i + 1] = v.y; }

    float4* yr = (float4*)(g_h + (size_t)r * D);
#pragma unroll 1
    for (int j4 = 0; j4 < D / 4; j4++) {
        float o[4];
#pragma unroll
        for (int c = 0; c < 4; c++) {
            int j = j4 * 4 + c;
            const ulonglong2* wr = (const ulonglong2*)(sW + j * D);
            ull a0 = 0, a1 = 0;
#pragma unroll
            for (int k = 0; k < D / 4; k++) {
                ulonglong2 w = wr[k];
                a0 = fma2(xp[2 * k], w.x, a0);
                a1 = fma2(xp[2 * k + 1], w.y, a1);
            }
            float2 f0 = unpack2(a0), f1 = unpack2(a1);
            o[c] = (f0.x + f0.y) + (f1.x + f1.y);
        }
        yr[j4] = make_float4(o[0], o[1], o[2], o[3]);
    }
}

// ---------------------------------------------------------------------------
// Edge pass: eh = edge_h @ W_fcr^T (per edge), stage in SMEM, then a
// channel-major phase does COALESCED atomics:
//   den[dst, j] += exp(eh_j);  num[dst, j] += exp(eh_j) * (h[src, j] + eh_j)
__global__ __launch_bounds__(128) void k_edge(
    const float* __restrict__ edge_h, const int* __restrict__ src,
    const int* __restrict__ dst, const float* __restrict__ W, int E) {
    extern __shared__ float smem[];
    float* sW  = smem;                    // 64*64
    float* sEH = smem + D * D;            // EPB*64, XOR-swizzled
    int* sSrc  = (int*)(sEH + EPB * D);   // EPB
    int* sDst  = sSrc + EPB;              // EPB

    int tid = threadIdx.x;
    for (int i = tid; i < D * D; i += blockDim.x) sW[i] = W[i];
    int e = blockIdx.x * EPB + tid;
    if (e < E) { sSrc[tid] = src[e]; sDst[tid] = dst[e]; }
    else       { sSrc[tid] = 0;      sDst[tid] = -1;     }
    __syncthreads();

    if (e < E) {
        ull xp[32];
        const ulonglong2* xr = (const ulonglong2*)(edge_h + (size_t)e * D);
#pragma unroll
        for (int i = 0; i < 16; i++) { ulonglong2 v = xr[i]; xp[2 * i] = v.x; xp[2 * i + 1] = v.y; }
#pragma unroll 1
        for (int j = 0; j < D; j++) {
            const ulonglong2* wr = (const ulonglong2*)(sW + j * D);
            ull a0 = 0, a1 = 0;
#pragma unroll
            for (int k = 0; k < 16; k++) {
                ulonglong2 w = wr[k];
                a0 = fma2(xp[2 * k], w.x, a0);
                a1 = fma2(xp[2 * k + 1], w.y, a1);
            }
            float2 f0 = unpack2(a0), f1 = unpack2(a1);
            sEH[tid * D + (j ^ (tid & 63))] = (f0.x + f0.y) + (f1.x + f1.y);
        }
    }
    __syncthreads();

    // Atomic phase: warp lanes cover consecutive channels of ONE edge.
    int j = tid & 63;
    int half = tid >> 6;
    for (int el = half; el < EPB; el += 2) {
        int d = sDst[el];
        if (d < 0) continue;
        int s = sSrc[el];
        float eh = sEH[el * D + (j ^ (el & 63))];
        float ex = __expf(eh);
        float hv = g_h[(size_t)s * D + j];          // coalesced, hits L2
        atomicAdd(g_den + (size_t)d * D + j, ex);   // coalesced 128B REDG
        atomicAdd(g_num + (size_t)d * D + j, ex * (hv + eh));
    }
}

// ---------------------------------------------------------------------------
// out = relu( deg>0 ? num/den + h @ loop_W : h )
__global__ __launch_bounds__(128) void k_final(
    const float* __restrict__ loop_W, float* __restrict__ out, int N) {
    __shared__ float sWt[D * D];  // transposed: sWt[j*D+k] = loop_W[k*D+j]
    for (int i = threadIdx.x; i < D * D; i += blockDim.x) {
        int k = i / D, j = i % D;
        sWt[j * D + k] = loop_W[i];
    }
    __syncthreads();
    int n = blockIdx.x * blockDim.x + threadIdx.x;
    if (n >= N) return;

    ull xp[32];
    const ulonglong2* xr = (const ulonglong2*)(g_h + (size_t)n * D);
#pragma unroll
    for (int i = 0; i < 16; i++) { ulonglong2 v = xr[i]; xp[2 * i] = v.x; xp[2 * i + 1] = v.y; }

    bool hasdeg = g_den[(size_t)n * D] > 0.f;
    const float* numr = g_num + (size_t)n * D;
    const float* denr = g_den + (size_t)n * D;
    float4* outr = (float4*)(out + (size_t)n * D);

#pragma unroll 1
    for (int j4 = 0; j4 < 16; j4++) {
        float o[4];
#pragma unroll
        for (int c = 0; c < 4; c++) {
            int j = j4 * 4 + c;
            float v;
            if (hasdeg) {
                const ulonglong2* wr = (const ulonglong2*)(sWt + j * D);
                ull a0 = 0, a1 = 0;
#pragma unroll
                for (int k = 0; k < 16; k++) {
                    ulonglong2 w = wr[k];
                    a0 = fma2(xp[2 * k], w.x, a0);
                    a1 = fma2(xp[2 * k + 1], w.y, a1);
                }
                float2 f0 = unpack2(a0), f1 = unpack2(a1);
                v = numr[j] / denr[j] + (f0.x + f0.y) + (f1.x + f1.y);
            } else {
                float2 hx = unpack2(xp[j / 2]);
                v = (j & 1) ? hx.y : hx.x;
            }
            o[c] = v > 0.f ? v : 0.f;
        }
        outr[j4] = make_float4(o[0], o[1], o[2], o[3]);
    }
}

// ---------------------------------------------------------------------------
extern "C" void kernel_launch(void* const* d_in, const int* in_sizes, int n_in,
                              void* d_out, int out_size) {
    const float* node_h = (const float*)d_in[0];
    const float* edge_h = (const float*)d_in[1];
    const int*   src    = (const int*)d_in[2];
    const int*   dst    = (const int*)d_in[3];
    const float* W_fc   = (const float*)d_in[4];
    const float* W_fcr  = (const float*)d_in[5];
    const float* loop_W = (const float*)d_in[6];
    float* out = (float*)d_out;

    int N = in_sizes[0] / D;
    int E = in_sizes[2];
    if (N > MAXN) N = MAXN;
    if (E > MAXE) E = MAXE;

    const int edge_smem = (D * D + EPB * D) * (int)sizeof(float) + 2 * EPB * (int)sizeof(int);
    // Idempotent; first (non-captured) correctness call sets it for all runs.
    cudaFuncSetAttribute(k_edge, cudaFuncAttributeMaxDynamicSharedMemorySize, edge_smem);

    int n4 = (N * D) / 4;
    k_zero<<<(n4 + 255) / 256, 256>>>(n4);
    k_node_gemm<<<(N + 127) / 128, 128>>>(node_h, W_fc, N);
    k_edge<<<(E + EPB - 1) / EPB, 128, edge_smem>>>(edge_h, src, dst, W_fcr, E);
    k_final<<<(N + 127) / 128, 128>>>(loop_W, out, N);
}

// round 2
// speedup vs baseline: 1.6734x; 1.6734x over previous
#include <cuda_runtime.h>
#include <cstdint>

#define D 64
#define MAXN 100000
#define MAXE 1600000
#define WAVE 128
#define NT 256
#define NWARP (NT / 32)

// Scratch (static device globals; no runtime allocation allowed)
__device__ float g_h[(size_t)MAXN * D];    // h = node_h @ W_fc^T
__device__ float g_num[(size_t)MAXN * D];  // sum ex*(h[src]+eh) per (dst, ch)
__device__ float g_den[(size_t)MAXN * D];  // sum ex per (dst, ch)

typedef unsigned long long ull;

__device__ __forceinline__ ull fma2(ull a, ull b, ull c) {
    ull d;
    asm("fma.rn.f32x2 %0, %1, %2, %3;" : "=l"(d) : "l"(a), "l"(b), "l"(c));
    return d;
}
__device__ __forceinline__ float2 unpack2(ull v) {
    float2 r;
    asm("mov.b64 {%0, %1}, %2;" : "=f"(r.x), "=f"(r.y) : "l"(v));
    return r;
}
__device__ __forceinline__ ull pack2(float lo, float hi) {
    ull r;
    asm("mov.b64 %0, {%1, %2};" : "=l"(r) : "f"(lo), "f"(hi));
    return r;
}
__device__ __forceinline__ void cp16(void* s, const void* g) {
    unsigned a = (unsigned)__cvta_generic_to_shared(s);
    asm volatile("cp.async.cg.shared.global [%0], [%1], 16;" :: "r"(a), "l"(g));
}
__device__ __forceinline__ void cp4(void* s, const void* g) {
    unsigned a = (unsigned)__cvta_generic_to_shared(s);
    asm volatile("cp.async.ca.shared.global [%0], [%1], 4;" :: "r"(a), "l"(g));
}
#define CP_COMMIT() asm volatile("cp.async.commit_group;" ::: "memory")
#define CP_WAIT1()  asm volatile("cp.async.wait_group 1;" ::: "memory")
#define CP_WAIT0()  asm volatile("cp.async.wait_group 0;" ::: "memory")

// ---------------------------------------------------------------------------
__global__ void k_zero(int n4) {  // n4 = N*D/4
    int i = blockIdx.x * blockDim.x + threadIdx.x;
    int stride = gridDim.x * blockDim.x;
    float4 z = make_float4(0.f, 0.f, 0.f, 0.f);
    float4* a = (float4*)g_num;
    float4* b = (float4*)g_den;
    for (; i < n4; i += stride) { a[i] = z; b[i] = z; }
}

// ---------------------------------------------------------------------------
// Load thread's two weight ROWS (j0 = 2*lane, j1 = j0+1) as f32x2 pairs over k.
__device__ __forceinline__ void load_w_rows(const float* __restrict__ W,
                                            int lane, ull* w0, ull* w1) {
    const ulonglong2* r0 = (const ulonglong2*)(W + (size_t)(2 * lane) * D);
    const ulonglong2* r1 = (const ulonglong2*)(W + (size_t)(2 * lane + 1) * D);
#pragma unroll
    for (int i = 0; i < 16; i++) {
        ulonglong2 v = r0[i]; w0[2 * i] = v.x; w0[2 * i + 1] = v.y;
        ulonglong2 u = r1[i]; w1[2 * i] = u.x; w1[2 * i + 1] = u.y;
    }
}

// GEMV for one row staged in smem (broadcast reads): returns (y_j0, y_j1)
__device__ __forceinline__ float2 gemv2(const float* sRow, const ull* w0, const ull* w1) {
    const ulonglong2* xr = (const ulonglong2*)sRow;
    ull a00 = 0, a01 = 0, a10 = 0, a11 = 0;
#pragma unroll
    for (int i = 0; i < 16; i++) {
        ulonglong2 v = xr[i];
        a00 = fma2(v.x, w0[2 * i], a00);
        a10 = fma2(v.x, w1[2 * i], a10);
        a01 = fma2(v.y, w0[2 * i + 1], a01);
        a11 = fma2(v.y, w1[2 * i + 1], a11);
    }
    float2 f0 = unpack2(a00), f1 = unpack2(a01);
    float y0 = (f0.x + f1.x) + (f0.y + f1.y);
    f0 = unpack2(a10); f1 = unpack2(a11);
    float y1 = (f0.x + f1.x) + (f0.y + f1.y);
    return make_float2(y0, y1);
}

// Stage WAVE contiguous rows of a (rows, 64) f32 matrix into smem buffer.
__device__ __forceinline__ void stage_rows(float* sXb, const float* __restrict__ G,
                                           size_t base, int nrows_total, int tid) {
#pragma unroll
    for (int i = 0; i < (WAVE * D / 4) / NT; i++) {  // 8 iters
        int idx = tid + i * NT;
        size_t r = base + (idx >> 4);
        if (r < (size_t)nrows_total)
            cp16(sXb + (size_t)idx * 4, G + r * D + (size_t)(idx & 15) * 4);
    }
}

// ---------------------------------------------------------------------------
// Edge pass: per edge, eh = W_fcr @ x; ex = exp(eh);
//   red: den[dst,j] += ex; num[dst,j] += ex*(h[src,j]+eh)
__global__ __launch_bounds__(NT, 1) void k_edge(
    const float* __restrict__ edge_h, const int* __restrict__ src,
    const int* __restrict__ dst, const float* __restrict__ W, int E) {
    extern __shared__ float smem[];
    float* sX = smem;                          // 2 * WAVE * D floats
    int* sS = (int*)(smem + 2 * WAVE * D);     // 2 * WAVE
    int* sDd = sS + 2 * WAVE;                  // 2 * WAVE

    int tid = threadIdx.x, lane = tid & 31, warp = tid >> 5;
    ull w0[32], w1[32];
    load_w_rows(W, lane, w0, w1);

    int nw = (E + WAVE - 1) / WAVE;
    int w = blockIdx.x;
    if (w >= nw) return;

    // prologue: stage wave w into buf 0
    {
        stage_rows(sX, edge_h, (size_t)w * WAVE, E, tid);
        if (tid < WAVE) {
            size_t e = (size_t)w * WAVE + tid;
            if (e < (size_t)E) { cp4(sS + tid, src + e); cp4(sDd + tid, dst + e); }
        }
        CP_COMMIT();
    }

    int buf = 0;
    for (; w < nw; w += gridDim.x, buf ^= 1) {
        int wn = w + gridDim.x;
        if (wn < nw) {
            int nb = buf ^ 1;
            stage_rows(sX + (size_t)nb * WAVE * D, edge_h, (size_t)wn * WAVE, E, tid);
            if (tid < WAVE) {
                size_t e = (size_t)wn * WAVE + tid;
                if (e < (size_t)E) { cp4(sS + nb * WAVE + tid, src + e); cp4(sDd + nb * WAVE + tid, dst + e); }
            }
            CP_COMMIT();
            CP_WAIT1();
        } else {
            CP_WAIT0();
        }
        __syncthreads();

        int ebase = w * WAVE;
        const float* sXb = sX + (size_t)buf * WAVE * D;
#pragma unroll 1
        for (int e = warp; e < WAVE; e += NWARP) {
            if (ebase + e >= E) break;
            int s = sS[buf * WAVE + e];
            int d = sDd[buf * WAVE + e];
            float2 hv = *(const float2*)(g_h + (size_t)s * D + 2 * lane);  // prefetch (L2)
            float2 eh = gemv2(sXb + (size_t)e * D, w0, w1);
            float ex0 = __expf(eh.x), ex1 = __expf(eh.y);
            float n0 = ex0 * (hv.x + eh.x), n1 = ex1 * (hv.y + eh.y);
            float* dp = g_den + (size_t)d * D + 2 * lane;
            float* np = g_num + (size_t)d * D + 2 * lane;
            asm volatile("red.relaxed.gpu.global.add.v2.f32 [%0], {%1, %2};"
                         :: "l"(dp), "f"(ex0), "f"(ex1) : "memory");
            asm volatile("red.relaxed.gpu.global.add.v2.f32 [%0], {%1, %2};"
                         :: "l"(np), "f"(n0), "f"(n1) : "memory");
        }
        __syncthreads();
    }
}

// ---------------------------------------------------------------------------
// g_h = node_h @ W_fc^T
__global__ __launch_bounds__(NT, 1) void k_node(
    const float* __restrict__ node_h, const float* __restrict__ W, int N) {
    extern __shared__ float smem[];
    float* sX = smem;

    int tid = threadIdx.x, lane = tid & 31, warp = tid >> 5;
    ull w0[32], w1[32];
    load_w_rows(W, lane, w0, w1);

    int nw = (N + WAVE - 1) / WAVE;
    int w = blockIdx.x;
    if (w >= nw) return;

    stage_rows(sX, node_h, (size_t)w * WAVE, N, tid);
    CP_COMMIT();

    int buf = 0;
    for (; w < nw; w += gridDim.x, buf ^= 1) {
        int wn = w + gridDim.x;
        if (wn < nw) {
            stage_rows(sX + (size_t)(buf ^ 1) * WAVE * D, node_h, (size_t)wn * WAVE, N, tid);
            CP_COMMIT();
            CP_WAIT1();
        } else {
            CP_WAIT0();
        }
        __syncthreads();

        int rbase = w * WAVE;
        const float* sXb = sX + (size_t)buf * WAVE * D;
#pragma unroll 1
        for (int r = warp; r < WAVE; r += NWARP) {
            if (rbase + r >= N) break;
            float2 y = gemv2(sXb + (size_t)r * D, w0, w1);
            *(float2*)(g_h + (size_t)(rbase + r) * D + 2 * lane) = y;
        }
        __syncthreads();
    }
}

// ---------------------------------------------------------------------------
// out = relu( deg>0 ? num/den + h @ loop_W : h )
// Thread owns output COLUMNS j0=2*lane, j1 of loop_W (packed over k-pairs).
__global__ __launch_bounds__(NT, 1) void k_final(
    const float* __restrict__ loop_W, float* __restrict__ out, int N) {
    extern __shared__ float smem[];
    float* sX = smem;

    int tid = threadIdx.x, lane = tid & 31, warp = tid >> 5;
    int j0 = 2 * lane;
    ull w0[32], w1[32];
#pragma unroll
    for (int kk = 0; kk < 32; kk++) {
        float2 a = *(const float2*)(loop_W + (size_t)(2 * kk) * D + j0);
        float2 b = *(const float2*)(loop_W + (size_t)(2 * kk + 1) * D + j0);
        w0[kk] = pack2(a.x, b.x);   // column j0, k-pair (2kk, 2kk+1)
        w1[kk] = pack2(a.y, b.y);   // column j1
    }

    int nw = (N + WAVE - 1) / WAVE;
    int w = blockIdx.x;
    if (w >= nw) return;

    stage_rows(sX, g_h, (size_t)w * WAVE, N, tid);
    CP_COMMIT();

    int buf = 0;
    for (; w < nw; w += gridDim.x, buf ^= 1) {
        int wn = w + gridDim.x;
        if (wn < nw) {
            stage_rows(sX + (size_t)(buf ^ 1) * WAVE * D, g_h, (size_t)wn * WAVE, N, tid);
            CP_COMMIT();
            CP_WAIT1();
        } else {
            CP_WAIT0();
        }
        __syncthreads();

        int rbase = w * WAVE;
        const float* sXb = sX + (size_t)buf * WAVE * D;
#pragma unroll 1
        for (int r = warp; r < WAVE; r += NWARP) {
            int n = rbase + r;
            if (n >= N) break;
            float2 den = *(const float2*)(g_den + (size_t)n * D + j0);  // prefetch
            float2 num = *(const float2*)(g_num + (size_t)n * D + j0);
            const float* sRow = sXb + (size_t)r * D;
            float2 g = gemv2(sRow, w0, w1);
            float2 hown = *(const float2*)(sRow + j0);
            float v0 = (den.x > 0.f) ? (__fdividef(num.x, den.x) + g.x) : hown.x;
            float v1 = (den.y > 0.f) ? (__fdividef(num.y, den.y) + g.y) : hown.y;
            v0 = fmaxf(v0, 0.f);
            v1 = fmaxf(v1, 0.f);
            *(float2*)(out + (size_t)n * D + j0) = make_float2(v0, v1);
        }
        __syncthreads();
    }
}

// ---------------------------------------------------------------------------
extern "C" void kernel_launch(void* const* d_in, const int* in_sizes, int n_in,
                              void* d_out, int out_size) {
    const float* node_h = (const float*)d_in[0];
    const float* edge_h = (const float*)d_in[1];
    const int*   src    = (const int*)d_in[2];
    const int*   dst    = (const int*)d_in[3];
    const float* W_fc   = (const float*)d_in[4];
    const float* W_fcr  = (const float*)d_in[5];
    const float* loop_W = (const float*)d_in[6];
    float* out = (float*)d_out;

    int N = in_sizes[0] / D;
    int E = in_sizes[2];
    if (N > MAXN) N = MAXN;
    if (E > MAXE) E = MAXE;

    const int EDGE_SMEM = 2 * WAVE * D * (int)sizeof(float) + 4 * WAVE * (int)sizeof(int);
    const int ROW_SMEM  = 2 * WAVE * D * (int)sizeof(float);
    cudaFuncSetAttribute(k_edge,  cudaFuncAttributeMaxDynamicSharedMemorySize, EDGE_SMEM);
    cudaFuncSetAttribute(k_node,  cudaFuncAttributeMaxDynamicSharedMemorySize, ROW_SMEM);
    cudaFuncSetAttribute(k_final, cudaFuncAttributeMaxDynamicSharedMemorySize, ROW_SMEM);

    int n4 = (N * D) / 4;
    k_zero<<<(n4 + 255) / 256, 256>>>(n4);
    k_node<<<152, NT, ROW_SMEM>>>(node_h, W_fc, N);
    k_edge<<<152, NT, EDGE_SMEM>>>(edge_h, src, dst, W_fcr, E);
    k_final<<<152, NT, ROW_SMEM>>>(loop_W, out, N);
}